// round 10
// baseline (speedup 1.0000x reference)
#include <cuda_runtime.h>
#include <cuda_fp16.h>
#include <cstdint>

// ---------------- problem constants ------------------------------------------
#define BATCH 8192
#define I_DIM 512
#define H_DIM 1024
#define D_DIM 8
#define G3H   3072
#define IP    576            // I + 64 pad (bias column at k=512)
#define HPAD  1088           // H + 64 pad (bias/ones column at k=1024)

// ---------------- GEMM tiling ------------------------------------------------
#define BM 128               // batch rows per CTA
#define BN 32                // hidden cols per CTA (per gate; 3 gates computed)
#define KC 64                // halves per K-chunk
#define NCHUNK1 9            // 576/64   (x @ W_ih^T)
#define NCHUNKS 26           // + 1088/64 (h' @ W_hh^T)
#define NSTAGE 3
#define SPITCH 144           // bytes per SMEM row (64 halves + 8 pad) -> conflict-free
#define SROWS (BM + 3 * BN)  // 128 A rows + 96 B rows = 224
#define STAGE_BYTES (SROWS * SPITCH)            // 32256
#define SMEM_ALLOC (NSTAGE * STAGE_BYTES + 256) // ~97KB -> 2 CTAs/SM
#define NTHREADS 256

// ---------------- device scratch ---------------------------------------------
__device__ __half g_x16[BATCH * IP];
__device__ __half g_h16[BATCH * HPAD];
__device__ __half g_wih[G3H * IP];
__device__ __half g_whh[G3H * HPAD];

// ---------------- PTX helpers ------------------------------------------------
__device__ __forceinline__ uint32_t smem_u32(const void* p) {
    uint32_t a;
    asm("{ .reg .u64 t; cvta.to.shared.u64 t, %1; cvt.u32.u64 %0, t; }"
        : "=r"(a) : "l"(p));
    return a;
}
__device__ __forceinline__ void cp16(uint32_t dst, const void* src) {
    asm volatile("cp.async.cg.shared.global [%0], [%1], 16;" :: "r"(dst), "l"(src));
}
#define CP_COMMIT() asm volatile("cp.async.commit_group;" ::: "memory")
#define CP_WAIT(n)  asm volatile("cp.async.wait_group %0;" :: "n"(n) : "memory")
#define LDSM4(r0, r1, r2, r3, addr) \
    asm volatile("ldmatrix.sync.aligned.m8n8.x4.shared.b16 {%0,%1,%2,%3}, [%4];" \
        : "=r"(r0), "=r"(r1), "=r"(r2), "=r"(r3) : "r"(addr))
#define MMA16816(acc, a0, a1, a2, a3, b0, b1) \
    asm volatile( \
        "mma.sync.aligned.m16n8k16.row.col.f32.f16.f16.f32 " \
        "{%0,%1,%2,%3}, {%4,%5,%6,%7}, {%8,%9}, {%0,%1,%2,%3};" \
        : "+f"((acc)[0]), "+f"((acc)[1]), "+f"((acc)[2]), "+f"((acc)[3]) \
        : "r"(a0), "r"(a1), "r"(a2), "r"(a3), "r"(b0), "r"(b1))

// ---------------- fused prep kernel ------------------------------------------
// blocks [0, 1024)      : gamma_h, 8 batch rows per block, w_gamma in registers
// blocks [1024, 2048)   : grid-stride fp32->fp16 converts with pad columns
#define GH_BLOCKS 1024
#define GH_ROWS 8
#define CV_BLOCKS 1024
#define PREP_BLOCKS (GH_BLOCKS + CV_BLOCKS)

__global__ void __launch_bounds__(256)
prep_kernel(const float* __restrict__ x,
            const float* __restrict__ delta,
            const float* __restrict__ h,
            const float* __restrict__ wih,
            const float* __restrict__ whh,
            const float* __restrict__ b_ih,
            const float* __restrict__ b_hh,
            const float* __restrict__ wg,
            const float* __restrict__ bg) {
    const int bid = blockIdx.x, t = threadIdx.x;
    if (bid < GH_BLOCKS) {
        // ---- gamma_h: h' = exp(-relu(delta @ Wg^T + bg)) * h ----
        const int j0 = t * 4;
        float w[4][8], b4[4];
#pragma unroll
        for (int k = 0; k < 4; k++) {
            const float4* w4 = reinterpret_cast<const float4*>(wg + (size_t)(j0 + k) * D_DIM);
            float4 lo = w4[0], hi = w4[1];
            w[k][0] = lo.x; w[k][1] = lo.y; w[k][2] = lo.z; w[k][3] = lo.w;
            w[k][4] = hi.x; w[k][5] = hi.y; w[k][6] = hi.z; w[k][7] = hi.w;
            b4[k] = bg[j0 + k];
        }
        const int r0 = bid * GH_ROWS;
#pragma unroll
        for (int b = r0; b < r0 + GH_ROWS; b++) {
            const float4* d4 = reinterpret_cast<const float4*>(delta + (size_t)b * D_DIM);
            float4 a0 = d4[0], a1 = d4[1];
            float4 hv = *reinterpret_cast<const float4*>(h + (size_t)b * H_DIM + j0);
            __half o4[4];
#pragma unroll
            for (int k = 0; k < 4; k++) {
                float s = a0.x * w[k][0] + a0.y * w[k][1] + a0.z * w[k][2] + a0.w * w[k][3]
                        + a1.x * w[k][4] + a1.y * w[k][5] + a1.z * w[k][6] + a1.w * w[k][7]
                        + b4[k];
                float g = __expf(-fmaxf(s, 0.0f));
                o4[k] = __float2half(g * (&hv.x)[k]);
            }
            *reinterpret_cast<uint2*>(g_h16 + (size_t)b * HPAD + j0) =
                *reinterpret_cast<uint2*>(o4);
            if (t < 16) {                        // pad cols 1024..1087
                int j = 1024 + t * 4;
                __half p4[4];
#pragma unroll
                for (int k = 0; k < 4; k++)
                    p4[k] = __float2half((j + k) == 1024 ? 1.0f : 0.0f);
                *reinterpret_cast<uint2*>(g_h16 + (size_t)b * HPAD + j) =
                    *reinterpret_cast<uint2*>(p4);
            }
        }
    } else {
        // ---- converts: x -> g_x16, W_ih -> g_wih, W_hh -> g_whh (4 halves/unit)
        const int n_x   = BATCH * IP / 4;
        const int n_wih = G3H * IP / 4;
        const int n_whh = G3H * HPAD / 4;
        const int total = n_x + n_wih + n_whh;
        const int start = (bid - GH_BLOCKS) * 256 + t;
        const int stride = CV_BLOCKS * 256;
        for (int u = start; u < total; u += stride) {
            const float* src; const float* bias; __half* dst; int sc, dc, v;
            if (u < n_x)               { v = u;                 src = x;   bias = nullptr; dst = g_x16; sc = I_DIM; dc = IP; }
            else if (u < n_x + n_wih)  { v = u - n_x;           src = wih; bias = b_ih;    dst = g_wih; sc = I_DIM; dc = IP; }
            else                       { v = u - n_x - n_wih;   src = whh; bias = b_hh;    dst = g_whh; sc = H_DIM; dc = HPAD; }
            int q = dc >> 2;
            int r = v / q, c0 = (v - r * q) << 2;
            float vv[4];
            if (c0 + 3 < sc) {
                float4 f = *reinterpret_cast<const float4*>(src + (size_t)r * sc + c0);
                vv[0] = f.x; vv[1] = f.y; vv[2] = f.z; vv[3] = f.w;
            } else {
#pragma unroll
                for (int k = 0; k < 4; k++) {
                    int c = c0 + k;
                    vv[k] = (c < sc) ? src[(size_t)r * sc + c]
                                     : ((c == sc) ? (bias ? bias[r] : 1.0f) : 0.0f);
                }
            }
            __half h4[4];
#pragma unroll
            for (int k = 0; k < 4; k++) h4[k] = __float2half(vv[k]);
            *reinterpret_cast<uint2*>(dst + (size_t)r * dc + c0) =
                *reinterpret_cast<uint2*>(h4);
        }
    }
}

// ---------------- chunk loader (cp.async, 1792 x 16B = 7 x 256) --------------
__device__ __forceinline__ void load_chunk(uint32_t stage_sb, int c,
                                           int bm, int jb, int tid) {
    const __half* A; const __half* B; int ld_; int kc;
    if (c < NCHUNK1) { A = g_x16; B = g_wih; ld_ = IP;   kc = c * KC; }
    else             { A = g_h16; B = g_whh; ld_ = HPAD; kc = (c - NCHUNK1) * KC; }
#pragma unroll
    for (int i = 0; i < 7; i++) {
        int u = tid + i * NTHREADS;              // 0..1791
        int row = u >> 3, cc = u & 7;            // 8 x 16B per 128B row
        const __half* src;
        if (row < BM) {
            src = A + (size_t)(bm + row) * ld_ + kc + cc * 8;
        } else {
            int rr = row - BM;                   // 0..95
            int g = rr >> 5, n = rr & 31;
            src = B + (size_t)(jb + n + g * H_DIM) * ld_ + kc + cc * 8;
        }
        cp16(stage_sb + (uint32_t)(row * SPITCH + cc * 16), src);
    }
    CP_COMMIT();
}

// ---------------- per-chunk MMA: software-pipelined fragments ----------------
// acc slots: 0 = r_pre (both phases), 1 = z_pre (both), 2 = i_n, 3 = h_n
// Warp tile: M=32, N=16 per gate. Each B ldmatrix.x4 feeds 4 MMAs.
template <int SN>
__device__ __forceinline__ void mma_chunk(float (&acc)[4][2][2][4],
                                          uint32_t stage_sb,
                                          uint32_t aoff0, uint32_t aoff1,
                                          uint32_t boff) {
    uint32_t a[2][2][4];   // [ks&1][m-subtile][reg]
    uint32_t b[2][4];      // [stage&1][reg]

    // preload stage 0: A(ks=0) both strips, B(g=0, ks=0)
    LDSM4(a[0][0][0], a[0][0][1], a[0][0][2], a[0][0][3], stage_sb + aoff0);
    LDSM4(a[0][1][0], a[0][1][1], a[0][1][2], a[0][1][3], stage_sb + aoff1);
    LDSM4(b[0][0], b[0][1], b[0][2], b[0][3], stage_sb + boff);

#pragma unroll
    for (int ks = 0; ks < 4; ks++) {
        const uint32_t kb = ks * 32;             // k-step byte offset
        const int ab = ks & 1;
#pragma unroll
        for (int g = 0; g < 3; g++) {
            const int bb = (ks * 3 + g) & 1;
            // ---- prefetch next stage's fragments ----
            if (g < 2) {
                LDSM4(b[bb ^ 1][0], b[bb ^ 1][1], b[bb ^ 1][2], b[bb ^ 1][3],
                      stage_sb + boff + (uint32_t)((g + 1) * 32 * SPITCH) + kb);
            } else if (ks < 3) {
                const uint32_t kb2 = kb + 32;
                LDSM4(a[ab ^ 1][0][0], a[ab ^ 1][0][1], a[ab ^ 1][0][2], a[ab ^ 1][0][3],
                      stage_sb + aoff0 + kb2);
                LDSM4(a[ab ^ 1][1][0], a[ab ^ 1][1][1], a[ab ^ 1][1][2], a[ab ^ 1][1][3],
                      stage_sb + aoff1 + kb2);
                LDSM4(b[bb ^ 1][0], b[bb ^ 1][1], b[bb ^ 1][2], b[bb ^ 1][3],
                      stage_sb + boff + kb2);
            }
            // ---- 4 MMAs with current fragments ----
            const int slot = (g == 0) ? 0 : (g == 1) ? 1 : SN;
            MMA16816(acc[slot][0][0], a[ab][0][0], a[ab][0][1], a[ab][0][2], a[ab][0][3],
                     b[bb][0], b[bb][1]);
            MMA16816(acc[slot][0][1], a[ab][0][0], a[ab][0][1], a[ab][0][2], a[ab][0][3],
                     b[bb][2], b[bb][3]);
            MMA16816(acc[slot][1][0], a[ab][1][0], a[ab][1][1], a[ab][1][2], a[ab][1][3],
                     b[bb][0], b[bb][1]);
            MMA16816(acc[slot][1][1], a[ab][1][0], a[ab][1][1], a[ab][1][2], a[ab][1][3],
                     b[bb][2], b[bb][3]);
        }
    }
}

// ---------------- main GEMM + GRU epilogue -----------------------------------
// 8 warps: (wid & 3) -> 32-row strip of BM, (wid >> 2) -> 16-col half of BN
// 2 CTAs per SM -> independent barrier domains interleave load/mma phases
__global__ void __launch_bounds__(NTHREADS, 2)
grud_mma_kernel(float* __restrict__ out) {
    extern __shared__ char smem_raw[];
    const uint32_t sb = (smem_u32(smem_raw) + 127) & ~127u;

    const int tid = threadIdx.x;
    const int wid = tid >> 5, lid = tid & 31;
    const int gid = lid >> 2, tig = lid & 3;      // groupID / thread-in-group
    const int wrow = (wid & 3) * 32;              // 32-row strip
    const int nq   = (wid >> 2) * 16;             // 16-col half of BN=32
    const int bm = blockIdx.x * BM, jb = blockIdx.y * BN;

    // ldmatrix per-lane offsets
    const int t8 = lid >> 3, ri = lid & 7;
    // A x4 tiles: {rows@k0, rows+8@k0, rows@k0+8, rows+8@k0+8}
    const uint32_t aoff0 = (uint32_t)((wrow +      (t8 & 1) * 8 + ri) * SPITCH + (t8 >> 1) * 16);
    const uint32_t aoff1 = (uint32_t)((wrow + 16 + (t8 & 1) * 8 + ri) * SPITCH + (t8 >> 1) * 16);
    // B x4 tiles: {n0-7@k0, n0-7@k0+8, n8-15@k0, n8-15@k0+8}
    const uint32_t boff = (uint32_t)((BM + nq + (t8 >> 1) * 8 + ri) * SPITCH + (t8 & 1) * 16);

    float acc[4][2][2][4];
#pragma unroll
    for (int s = 0; s < 4; s++)
#pragma unroll
        for (int m = 0; m < 2; m++)
#pragma unroll
            for (int n = 0; n < 2; n++)
#pragma unroll
                for (int e = 0; e < 4; e++) acc[s][m][n][e] = 0.0f;

    // prologue: fill 2 stages
    load_chunk(sb + 0 * STAGE_BYTES, 0, bm, jb, tid);
    load_chunk(sb + 1 * STAGE_BYTES, 1, bm, jb, tid);

#pragma unroll 1
    for (int c = 0; c < NCHUNKS; c++) {
        if (c < NCHUNKS - 1) CP_WAIT(1);          // chunk c's loads complete
        else                 CP_WAIT(0);
        __syncthreads();                          // all warps done with chunk c-1

        if (c + 2 < NCHUNKS)                      // stage (c+2)%3 freed at iter c-1
            load_chunk(sb + ((c + 2) % 3) * STAGE_BYTES, c + 2, bm, jb, tid);

        const uint32_t stage_sb = sb + (c % 3) * STAGE_BYTES;
        if (c < NCHUNK1) mma_chunk<2>(acc, stage_sb, aoff0, aoff1, boff);
        else             mma_chunk<3>(acc, stage_sb, aoff0, aoff1, boff);
    }

    // ---- epilogue: GRU math straight from registers -------------------------
#pragma unroll
    for (int m = 0; m < 2; m++) {
        const int r0 = bm + wrow + m * 16 + gid;  // rows r0 and r0+8
#pragma unroll
        for (int n = 0; n < 2; n++) {
            const int col = jb + nq + n * 8 + tig * 2;
            __half2 ha = *(const __half2*)(g_h16 + (size_t)r0 * HPAD + col);
            __half2 hb = *(const __half2*)(g_h16 + (size_t)(r0 + 8) * HPAD + col);
            float hq[4] = { __half2float(ha.x), __half2float(ha.y),
                            __half2float(hb.x), __half2float(hb.y) };
            float o[4];
#pragma unroll
            for (int e = 0; e < 4; e++) {
                float r  = 1.0f / (1.0f + __expf(-acc[0][m][n][e]));
                float z  = 1.0f / (1.0f + __expf(-acc[1][m][n][e]));
                float na = acc[2][m][n][e] + r * acc[3][m][n][e];
                float nn = 2.0f / (1.0f + __expf(-2.0f * na)) - 1.0f;   // tanh
                o[e] = nn + z * (hq[e] - nn);
            }
            *(float2*)(out + (size_t)r0 * H_DIM + col)       = make_float2(o[0], o[1]);
            *(float2*)(out + (size_t)(r0 + 8) * H_DIM + col) = make_float2(o[2], o[3]);
        }
    }
}

// ---------------- launch ------------------------------------------------------
extern "C" void kernel_launch(void* const* d_in, const int* in_sizes, int n_in,
                              void* d_out, int out_size) {
    const float* x         = (const float*)d_in[0];
    const float* delta     = (const float*)d_in[1];
    const float* h         = (const float*)d_in[2];
    const float* weight_ih = (const float*)d_in[3];
    const float* weight_hh = (const float*)d_in[4];
    const float* bias_ih   = (const float*)d_in[5];
    const float* bias_hh   = (const float*)d_in[6];
    const float* w_gamma   = (const float*)d_in[7];
    const float* b_gamma   = (const float*)d_in[8];
    float* out = (float*)d_out;

    cudaFuncSetAttribute(grud_mma_kernel,
                         cudaFuncAttributeMaxDynamicSharedMemorySize, SMEM_ALLOC);

    prep_kernel<<<PREP_BLOCKS, 256>>>(x, delta, h, weight_ih, weight_hh,
                                      bias_ih, bias_hh, w_gamma, b_gamma);

    dim3 grid(BATCH / BM, H_DIM / BN);   // (64, 32) = 2048 CTAs, 2/SM
    grud_mma_kernel<<<grid, NTHREADS, SMEM_ALLOC>>>(out);
}

// round 12
// speedup vs baseline: 1.6885x; 1.6885x over previous
#include <cuda_runtime.h>
#include <cuda_fp16.h>
#include <cstdint>

// ---------------- problem constants ------------------------------------------
#define BATCH 8192
#define I_DIM 512
#define H_DIM 1024
#define D_DIM 8
#define G3H   3072
#define IP    576            // I + 64 pad (bias column at k=512)
#define HPAD  1088           // H + 64 pad (bias/ones column at k=1024)

// ---------------- GEMM tiling ------------------------------------------------
#define BM 128               // batch rows per CTA
#define BN 64                // hidden cols per CTA (per gate; 3 gates computed)
#define KC 64                // halves per K-chunk
#define NCHUNK1 9            // 576/64   (x @ W_ih^T)
#define NCHUNKS 26           // + 1088/64 (h' @ W_hh^T)
#define NSTAGE 4
#define SPITCH 144           // bytes per SMEM row (64 halves + 8 pad) -> conflict-free
#define SROWS (BM + 3 * BN)  // 128 A rows + 192 B rows = 320
#define STAGE_BYTES (SROWS * SPITCH)            // 46080
#define BAR_BYTES 64
#define SMEM_ALLOC (NSTAGE * STAGE_BYTES + BAR_BYTES + 256)
#define NTHREADS 576         // 16 consumer warps + 2 producer warps
#define NCONS 512
#define NPROD 64

// ---------------- device scratch ---------------------------------------------
__device__ __half g_x16[BATCH * IP];
__device__ __half g_h16[BATCH * HPAD];
__device__ __half g_wih[G3H * IP];
__device__ __half g_whh[G3H * HPAD];

// ---------------- PTX helpers ------------------------------------------------
__device__ __forceinline__ uint32_t smem_u32(const void* p) {
    uint32_t a;
    asm("{ .reg .u64 t; cvta.to.shared.u64 t, %1; cvt.u32.u64 %0, t; }"
        : "=r"(a) : "l"(p));
    return a;
}
__device__ __forceinline__ void cp16(uint32_t dst, const void* src) {
    asm volatile("cp.async.cg.shared.global [%0], [%1], 16;" :: "r"(dst), "l"(src));
}
#define MBAR_INIT(a, c)  asm volatile("mbarrier.init.shared.b64 [%0], %1;" :: "r"(a), "r"(c) : "memory")
#define MBAR_ARRIVE(a)   asm volatile("mbarrier.arrive.shared.b64 _, [%0];" :: "r"(a) : "memory")
#define CP_MBAR_ARRIVE(a) asm volatile("cp.async.mbarrier.arrive.noinc.shared.b64 [%0];" :: "r"(a) : "memory")
__device__ __forceinline__ void mbar_wait(uint32_t mbar, uint32_t parity) {
    asm volatile(
        "{\n\t.reg .pred P;\n"
        "LAB_%=:\n\t"
        "mbarrier.try_wait.parity.acquire.cta.shared::cta.b64 P, [%0], %1, 0x989680;\n\t"
        "@!P bra LAB_%=;\n\t}"
        :: "r"(mbar), "r"(parity) : "memory");
}
#define LDSM4(r0, r1, r2, r3, addr) \
    asm volatile("ldmatrix.sync.aligned.m8n8.x4.shared.b16 {%0,%1,%2,%3}, [%4];" \
        : "=r"(r0), "=r"(r1), "=r"(r2), "=r"(r3) : "r"(addr))
#define MMA16816(acc, a0, a1, a2, a3, b0, b1) \
    asm volatile( \
        "mma.sync.aligned.m16n8k16.row.col.f32.f16.f16.f32 " \
        "{%0,%1,%2,%3}, {%4,%5,%6,%7}, {%8,%9}, {%0,%1,%2,%3};" \
        : "+f"((acc)[0]), "+f"((acc)[1]), "+f"((acc)[2]), "+f"((acc)[3]) \
        : "r"(a0), "r"(a1), "r"(a2), "r"(a3), "r"(b0), "r"(b1))

// ---------------- fused prep kernel ------------------------------------------
#define GH_BLOCKS 1024
#define GH_ROWS 8
#define CV_BLOCKS 1024
#define PREP_BLOCKS (GH_BLOCKS + CV_BLOCKS)

__global__ void __launch_bounds__(256)
prep_kernel(const float* __restrict__ x,
            const float* __restrict__ delta,
            const float* __restrict__ h,
            const float* __restrict__ wih,
            const float* __restrict__ whh,
            const float* __restrict__ b_ih,
            const float* __restrict__ b_hh,
            const float* __restrict__ wg,
            const float* __restrict__ bg) {
    const int bid = blockIdx.x, t = threadIdx.x;
    if (bid < GH_BLOCKS) {
        const int j0 = t * 4;
        float w[4][8], b4[4];
#pragma unroll
        for (int k = 0; k < 4; k++) {
            const float4* w4 = reinterpret_cast<const float4*>(wg + (size_t)(j0 + k) * D_DIM);
            float4 lo = w4[0], hi = w4[1];
            w[k][0] = lo.x; w[k][1] = lo.y; w[k][2] = lo.z; w[k][3] = lo.w;
            w[k][4] = hi.x; w[k][5] = hi.y; w[k][6] = hi.z; w[k][7] = hi.w;
            b4[k] = bg[j0 + k];
        }
        const int r0 = bid * GH_ROWS;
#pragma unroll
        for (int b = r0; b < r0 + GH_ROWS; b++) {
            const float4* d4 = reinterpret_cast<const float4*>(delta + (size_t)b * D_DIM);
            float4 a0 = d4[0], a1 = d4[1];
            float4 hv = *reinterpret_cast<const float4*>(h + (size_t)b * H_DIM + j0);
            __half o4[4];
#pragma unroll
            for (int k = 0; k < 4; k++) {
                float s = a0.x * w[k][0] + a0.y * w[k][1] + a0.z * w[k][2] + a0.w * w[k][3]
                        + a1.x * w[k][4] + a1.y * w[k][5] + a1.z * w[k][6] + a1.w * w[k][7]
                        + b4[k];
                float g = __expf(-fmaxf(s, 0.0f));
                o4[k] = __float2half(g * (&hv.x)[k]);
            }
            *reinterpret_cast<uint2*>(g_h16 + (size_t)b * HPAD + j0) =
                *reinterpret_cast<uint2*>(o4);
            if (t < 16) {                        // pad cols 1024..1087
                int j = 1024 + t * 4;
                __half p4[4];
#pragma unroll
                for (int k = 0; k < 4; k++)
                    p4[k] = __float2half((j + k) == 1024 ? 1.0f : 0.0f);
                *reinterpret_cast<uint2*>(g_h16 + (size_t)b * HPAD + j) =
                    *reinterpret_cast<uint2*>(p4);
            }
        }
    } else {
        const int n_x   = BATCH * IP / 4;
        const int n_wih = G3H * IP / 4;
        const int n_whh = G3H * HPAD / 4;
        const int total = n_x + n_wih + n_whh;
        const int start = (bid - GH_BLOCKS) * 256 + t;
        const int stride = CV_BLOCKS * 256;
        for (int u = start; u < total; u += stride) {
            const float* src; const float* bias; __half* dst; int sc, dc, v;
            if (u < n_x)               { v = u;                 src = x;   bias = nullptr; dst = g_x16; sc = I_DIM; dc = IP; }
            else if (u < n_x + n_wih)  { v = u - n_x;           src = wih; bias = b_ih;    dst = g_wih; sc = I_DIM; dc = IP; }
            else                       { v = u - n_x - n_wih;   src = whh; bias = b_hh;    dst = g_whh; sc = H_DIM; dc = HPAD; }
            int q = dc >> 2;
            int r = v / q, c0 = (v - r * q) << 2;
            float vv[4];
            if (c0 + 3 < sc) {
                float4 f = *reinterpret_cast<const float4*>(src + (size_t)r * sc + c0);
                vv[0] = f.x; vv[1] = f.y; vv[2] = f.z; vv[3] = f.w;
            } else {
#pragma unroll
                for (int k = 0; k < 4; k++) {
                    int c = c0 + k;
                    vv[k] = (c < sc) ? src[(size_t)r * sc + c]
                                     : ((c == sc) ? (bias ? bias[r] : 1.0f) : 0.0f);
                }
            }
            __half h4[4];
#pragma unroll
            for (int k = 0; k < 4; k++) h4[k] = __float2half(vv[k]);
            *reinterpret_cast<uint2*>(dst + (size_t)r * dc + c0) =
                *reinterpret_cast<uint2*>(h4);
        }
    }
}

// ---------------- producer chunk loader (64 threads, 40 cp16 each) ----------
__device__ __forceinline__ void load_chunk_p(uint32_t stage_sb, int c,
                                             int bm, int jb, int p) {
    const __half* A; const __half* B; int ld_; int kc;
    if (c < NCHUNK1) { A = g_x16; B = g_wih; ld_ = IP;   kc = c * KC; }
    else             { A = g_h16; B = g_whh; ld_ = HPAD; kc = (c - NCHUNK1) * KC; }
#pragma unroll
    for (int i = 0; i < 40; i++) {
        int u = p + i * NPROD;                   // 0..2559
        int row = u >> 3, cc = u & 7;            // 8 x 16B per 128B row
        const __half* src;
        if (row < BM) {
            src = A + (size_t)(bm + row) * ld_ + kc + cc * 8;
        } else {
            int rr = row - BM;                   // 0..191
            int g = rr >> 6, n = rr & 63;
            src = B + (size_t)(jb + n + g * H_DIM) * ld_ + kc + cc * 8;
        }
        cp16(stage_sb + (uint32_t)(row * SPITCH + cc * 16), src);
    }
}

// ---------------- per-chunk MMA: M=32/warp, N=16/warp per gate ---------------
// acc slots: 0 = r_pre (both phases), 1 = z_pre (both), 2 = i_n, 3 = h_n
template <int SN>
__device__ __forceinline__ void mma_chunk(float (&acc)[4][2][2][4],
                                          uint32_t stage_sb,
                                          uint32_t aoff0, uint32_t aoff1,
                                          uint32_t boff) {
#pragma unroll
    for (int ks = 0; ks < 4; ks++) {
        const uint32_t kb = ks * 32;             // k0*2 bytes
        uint32_t a0[4], a1[4];
        LDSM4(a0[0], a0[1], a0[2], a0[3], stage_sb + aoff0 + kb);  // rows wrow..+15
        LDSM4(a1[0], a1[1], a1[2], a1[3], stage_sb + aoff1 + kb);  // rows wrow+16..+31
#pragma unroll
        for (int g = 0; g < 3; g++) {
            const int slot = (g == 0) ? 0 : (g == 1) ? 1 : SN;
            uint32_t b0, b1, b2, b3;
            LDSM4(b0, b1, b2, b3,
                  stage_sb + boff + (uint32_t)(g * 64 * SPITCH) + kb);
            MMA16816(acc[slot][0][0], a0[0], a0[1], a0[2], a0[3], b0, b1);
            MMA16816(acc[slot][0][1], a0[0], a0[1], a0[2], a0[3], b2, b3);
            MMA16816(acc[slot][1][0], a1[0], a1[1], a1[2], a1[3], b0, b1);
            MMA16816(acc[slot][1][1], a1[0], a1[1], a1[2], a1[3], b2, b3);
        }
    }
}

// ---------------- main GEMM + GRU epilogue -----------------------------------
// 18 warps: 0-15 consumers ((wid&3) -> 32-row strip, (wid>>2) -> 16-col quarter)
//           16-17 producers (all cp.async, self-throttled on empty mbarriers)
__global__ void __launch_bounds__(NTHREADS, 1)
grud_mma_kernel(float* __restrict__ out) {
    extern __shared__ char smem_raw[];
    const uint32_t sb = (smem_u32(smem_raw) + 127) & ~127u;
    const uint32_t bar = sb + NSTAGE * STAGE_BYTES;   // full[s]=bar+16s, empty=+8

    const int tid = threadIdx.x;
    const int wid = tid >> 5, lid = tid & 31;
    const int bm = blockIdx.x * BM, jb = blockIdx.y * BN;

    if (tid == 0) {
#pragma unroll
        for (int s = 0; s < NSTAGE; s++) {
            MBAR_INIT(bar + s * 16, NPROD);      // full: one cp-arrive per producer thread
            MBAR_INIT(bar + s * 16 + 8, 16);     // empty: one arrive per consumer warp
        }
    }
    __syncthreads();                             // only CTA-wide barrier in the kernel

    if (wid >= 16) {
        // ================= producers =================
        const int p = tid - NCONS;               // 0..63
#pragma unroll 1
        for (int c = 0; c < NCHUNKS; c++) {
            const int s = c & 3;
            const uint32_t pw = (((uint32_t)c >> 2) & 1u) ^ 1u;
            mbar_wait(bar + s * 16 + 8, pw);     // stage free? (first pass immediate)
            load_chunk_p(sb + s * STAGE_BYTES, c, bm, jb, p);
            CP_MBAR_ARRIVE(bar + s * 16);        // arrive on full when copies land
        }
        return;
    }

    // ================= consumers =================
    const int gid = lid >> 2, tig = lid & 3;
    const int wrow = (wid & 3) * 32;
    const int nq   = (wid >> 2) * 16;
    const int t8 = lid >> 3, ri = lid & 7;
    const uint32_t aoff0 = (uint32_t)((wrow +      (t8 & 1) * 8 + ri) * SPITCH + (t8 >> 1) * 16);
    const uint32_t aoff1 = (uint32_t)((wrow + 16 + (t8 & 1) * 8 + ri) * SPITCH + (t8 >> 1) * 16);
    const uint32_t boff = (uint32_t)((BM + nq + (t8 >> 1) * 8 + ri) * SPITCH + (t8 & 1) * 16);

    float acc[4][2][2][4];
#pragma unroll
    for (int s = 0; s < 4; s++)
#pragma unroll
        for (int m = 0; m < 2; m++)
#pragma unroll
            for (int n = 0; n < 2; n++)
#pragma unroll
                for (int e = 0; e < 4; e++) acc[s][m][n][e] = 0.0f;

#pragma unroll 1
    for (int c = 0; c < NCHUNKS; c++) {
        const int s = c & 3;
        const uint32_t w = ((uint32_t)c >> 2) & 1u;
        mbar_wait(bar + s * 16, w);              // wait stage full
        const uint32_t stage_sb = sb + s * STAGE_BYTES;
        if (c < NCHUNK1) mma_chunk<2>(acc, stage_sb, aoff0, aoff1, boff);
        else             mma_chunk<3>(acc, stage_sb, aoff0, aoff1, boff);
        if (lid == 0) MBAR_ARRIVE(bar + s * 16 + 8);   // stage consumed
    }

    // ---- epilogue: GRU math straight from registers -------------------------
#pragma unroll
    for (int m = 0; m < 2; m++) {
        const int r0 = bm + wrow + m * 16 + gid;  // rows r0 and r0+8
#pragma unroll
        for (int n = 0; n < 2; n++) {
            const int col = jb + nq + n * 8 + tig * 2;
            __half2 ha = *(const __half2*)(g_h16 + (size_t)r0 * HPAD + col);
            __half2 hb = *(const __half2*)(g_h16 + (size_t)(r0 + 8) * HPAD + col);
            float hq[4] = { __half2float(ha.x), __half2float(ha.y),
                            __half2float(hb.x), __half2float(hb.y) };
            float o[4];
#pragma unroll
            for (int e = 0; e < 4; e++) {
                float r  = 1.0f / (1.0f + __expf(-acc[0][m][n][e]));
                float z  = 1.0f / (1.0f + __expf(-acc[1][m][n][e]));
                float na = acc[2][m][n][e] + r * acc[3][m][n][e];
                float nn = 2.0f / (1.0f + __expf(-2.0f * na)) - 1.0f;   // tanh
                o[e] = nn + z * (hq[e] - nn);
            }
            *(float2*)(out + (size_t)r0 * H_DIM + col)       = make_float2(o[0], o[1]);
            *(float2*)(out + (size_t)(r0 + 8) * H_DIM + col) = make_float2(o[2], o[3]);
        }
    }
}

// ---------------- launch ------------------------------------------------------
extern "C" void kernel_launch(void* const* d_in, const int* in_sizes, int n_in,
                              void* d_out, int out_size) {
    const float* x         = (const float*)d_in[0];
    const float* delta     = (const float*)d_in[1];
    const float* h         = (const float*)d_in[2];
    const float* weight_ih = (const float*)d_in[3];
    const float* weight_hh = (const float*)d_in[4];
    const float* bias_ih   = (const float*)d_in[5];
    const float* bias_hh   = (const float*)d_in[6];
    const float* w_gamma   = (const float*)d_in[7];
    const float* b_gamma   = (const float*)d_in[8];
    float* out = (float*)d_out;

    cudaFuncSetAttribute(grud_mma_kernel,
                         cudaFuncAttributeMaxDynamicSharedMemorySize, SMEM_ALLOC);

    prep_kernel<<<PREP_BLOCKS, 256>>>(x, delta, h, weight_ih, weight_hh,
                                      bias_ih, bias_hh, w_gamma, b_gamma);

    dim3 grid(BATCH / BM, H_DIM / BN);   // (64, 16) = 1024 CTAs, 1/SM
    grud_mma_kernel<<<grid, NTHREADS, SMEM_ALLOC>>>(out);
}